// round 1
// baseline (speedup 1.0000x reference)
#include <cuda_runtime.h>

#define NC    6
#define CF    64
#define Hh    88
#define Ww    160
#define HWp   (Hh*Ww)          // 14080
#define XD    100
#define YD    100
#define ZD    20
#define NVOX  (XD*YD*ZD)       // 200000
#define VPRE  64
#define WARPS 8
#define NBLK  456              // 152 SMs * 3 blocks

// scratch: channel-last features [cam][H][W][C]
__device__ float g_featT[NC * HWp * CF];

// dynamic smem layout (bytes):
//  float2 wno[65*32]   16640
//  float2 wo [130*32]  33280
//  float  bno[64]        256
//  float  bo [64]        256
//  float  E  [96]        384
//  float  K  [96]        384
//  float  feat[8*132]   4224
//  float  sout[64*9]    2304
#define SMEM_BYTES (16640 + 33280 + 256 + 256 + 384 + 384 + 4224 + 2304)

__global__ void transpose_kernel(const float* __restrict__ feat) {
    __shared__ float tile[32][33];
    int cam = blockIdx.z;
    int c0  = blockIdx.y * 32;       // 0 or 32
    int p0  = blockIdx.x * 32;       // pixel tile (HWp = 32*440 exactly)
    int tx = threadIdx.x, ty = threadIdx.y;
    const float* src = feat + (size_t)cam * CF * HWp;
#pragma unroll
    for (int i = ty; i < 32; i += 8)
        tile[i][tx] = src[(c0 + i) * HWp + p0 + tx];
    __syncthreads();
    float* dst = g_featT + (size_t)cam * HWp * CF;
#pragma unroll
    for (int i = ty; i < 32; i += 8)
        dst[(p0 + i) * CF + c0 + tx] = tile[tx][i];
}

__global__ __launch_bounds__(256) void fuse_kernel(
    const float* __restrict__ mask,   // [6,1,88,160]
    const float* __restrict__ Kin,    // [6,4,4]
    const float* __restrict__ Ein,    // [6,4,4]
    const float* __restrict__ w_no,   // [64,65]
    const float* __restrict__ b_no,   // [64]
    const float* __restrict__ w_o,    // [64,130]
    const float* __restrict__ b_o,    // [64]
    float* __restrict__ out)          // [64, NVOX]
{
    extern __shared__ float smem[];
    float2* s_wno = (float2*)smem;                    // 65*32
    float2* s_wo  = s_wno + 65 * 32;                  // 130*32
    float*  s_bno = (float*)(s_wo + 130 * 32);        // 64
    float*  s_bo  = s_bno + 64;                       // 64
    float*  s_E   = s_bo + 64;                        // 96
    float*  s_K   = s_E + 96;                         // 96
    float*  s_feat= s_K + 96;                         // 8*132
    float*  s_out = s_feat + WARPS * 132;             // 64*9

    int tid = threadIdx.x;
    for (int i = tid; i < 65 * 32; i += 256) {
        int c = i >> 5, l = i & 31;
        s_wno[i] = make_float2(w_no[l * 65 + c], w_no[(l + 32) * 65 + c]);
    }
    for (int i = tid; i < 130 * 32; i += 256) {
        int c = i >> 5, l = i & 31;
        s_wo[i] = make_float2(w_o[l * 130 + c], w_o[(l + 32) * 130 + c]);
    }
    if (tid < 64) { s_bno[tid] = b_no[tid]; s_bo[tid] = b_o[tid]; }
    if (tid < 96) { s_E[tid] = Ein[tid]; s_K[tid] = Kin[tid]; }
    __syncthreads();

    int warp = tid >> 5, lane = tid & 31;
    int gw0 = blockIdx.x * WARPS + warp;
    int nwarps = gridDim.x * WARPS;
    float* feat = s_feat + warp * 132;   // group0 @0 (65 used), group1 @66 (65 used)
    int T = (NVOX + nwarps - 1) / nwarps;

    for (int t = 0; t < T; t++) {
        int n = gw0 + t * nwarps;
        float o0 = 0.f, o1 = 0.f;
        if (n < NVOX) {
            int x = n % XD;
            int y = (n / XD) % YD;
            int z = n / (XD * YD);
            float X = -50.f + (float)x;
            float Y = -50.f + (float)y;
            float Z = -15.f + 1.5f * (float)z;

            feat[lane] = 0.f; feat[lane + 32] = 0.f;
            feat[lane + 64] = 0.f; feat[lane + 96] = 0.f;
            if (lane < 4) feat[128 + lane] = 0.f;
            __syncwarp();

            int count = 0;
#pragma unroll
            for (int cam = 0; cam < NC; cam++) {
                const float* E  = s_E + cam * 16;
                const float* Km = s_K + cam * 16;
                float vx = E[0] * X + E[1] * Y + E[2]  * Z + E[3];
                float vy = E[4] * X + E[5] * Y + E[6]  * Z + E[7];
                float vz = E[8] * X + E[9] * Y + E[10] * Z + E[11];
                float cx = Km[0] * vx + Km[1] * vy + Km[2] * vz;
                float cy = Km[4] * vx + Km[5] * vy + Km[6] * vz;
                float cz = Km[8] * vx + Km[9] * vy + Km[10] * vz;
                float denom = cz + 1e-8f;
                float px = __fdiv_rn(cx, denom);
                float py = __fdiv_rn(cy, denom);
                float gx = (__fdiv_rn(px, 159.f) - 0.5f) * 2.f;
                float gy = (__fdiv_rn(py,  87.f) - 0.5f) * 2.f;
                if (gx > 1.f || gx < -1.f || gy > 1.f || gy < -1.f) continue; // oob
                if (!(vz > 0.f)) continue;                                    // depth
                float xs = (gx + 1.f) * 0.5f * 159.f;
                float ys = (gy + 1.f) * 0.5f * 87.f;
                // nearest mask (round half-to-even, zeros padding)
                float xr = rintf(xs), yr = rintf(ys);
                if (!(xr >= 0.f && xr <= 159.f && yr >= 0.f && yr <= 87.f)) continue;
                float mv = __ldg(mask + cam * HWp + (int)yr * Ww + (int)xr);
                if (!(mv > 0.5f)) continue;
                count++;
                int grp = (cam == 0 || cam == 3 || cam == 4) ? 0 : 1;
                float* fg = feat + grp * 66;
                // bilinear (align_corners, zeros padding)
                float x0 = floorf(xs), y0 = floorf(ys);
                float wx1 = xs - x0, wx0 = 1.f - wx1;
                float wy1 = ys - y0, wy0 = 1.f - wy1;
                float ax = 0.f, ay = 0.f;
                const float2* base = (const float2*)(g_featT + (size_t)cam * HWp * CF);
#pragma unroll
                for (int corner = 0; corner < 4; corner++) {
                    float xi = x0 + (float)(corner & 1);
                    float yi = y0 + (float)(corner >> 1);
                    if (xi >= 0.f && xi <= 159.f && yi >= 0.f && yi <= 87.f) {
                        float w = ((corner & 1) ? wx1 : wx0) * ((corner >> 1) ? wy1 : wy0);
                        int pixi = (int)yi * Ww + (int)xi;
                        float2 v = __ldg(base + pixi * 32 + lane);
                        ax += w * v.x;
                        ay += w * v.y;
                    }
                }
                fg[2 * lane]     += ax;
                fg[2 * lane + 1] += ay;
                if (lane == 0) fg[64] += __fdiv_rn(vz, 100.f);
            }
            __syncwarp();

            if (count == 1) {
#pragma unroll 5
                for (int c = 0; c < 65; c++) {
                    float f = feat[c] + feat[66 + c];
                    float2 w = s_wno[c * 32 + lane];
                    o0 = fmaf(w.x, f, o0);
                    o1 = fmaf(w.y, f, o1);
                }
                o0 += s_bno[lane]; o1 += s_bno[lane + 32];
                o0 = o0 > 0.f ? o0 : expm1f(o0);
                o1 = o1 > 0.f ? o1 : expm1f(o1);
            } else if (count == 2) {
#pragma unroll 5
                for (int c = 0; c < 65; c++) {
                    float f = feat[c];
                    float2 w = s_wo[c * 32 + lane];
                    o0 = fmaf(w.x, f, o0);
                    o1 = fmaf(w.y, f, o1);
                }
#pragma unroll 5
                for (int c = 0; c < 65; c++) {
                    float f = feat[66 + c];
                    float2 w = s_wo[(65 + c) * 32 + lane];
                    o0 = fmaf(w.x, f, o0);
                    o1 = fmaf(w.y, f, o1);
                }
                o0 += s_bo[lane]; o1 += s_bo[lane + 32];
                o0 = o0 > 0.f ? o0 : expm1f(o0);
                o1 = o1 > 0.f ? o1 : expm1f(o1);
            }
            s_out[lane * 9 + warp]        = o0;
            s_out[(lane + 32) * 9 + warp] = o1;
        }
        __syncthreads();
        // block-staged coalesced output write: 8 consecutive voxels per block-iter
        int nbase = blockIdx.x * WARPS + t * nwarps;
#pragma unroll
        for (int i = tid; i < 512; i += 256) {
            int o = i >> 3, v = i & 7;
            int nn = nbase + v;
            if (nn < NVOX) out[(size_t)o * NVOX + nn] = s_out[o * 9 + v];
        }
        __syncthreads();
    }
}

extern "C" void kernel_launch(void* const* d_in, const int* in_sizes, int n_in,
                              void* d_out, int out_size) {
    const float* feat = (const float*)d_in[0];
    const float* mask = (const float*)d_in[1];
    const float* K    = (const float*)d_in[2];
    const float* ext  = (const float*)d_in[3];
    const float* w_no = (const float*)d_in[4];
    const float* b_no = (const float*)d_in[5];
    const float* w_o  = (const float*)d_in[6];
    const float* b_o  = (const float*)d_in[7];
    float* out = (float*)d_out;

    dim3 tg(HWp / 32, CF / 32, NC);   // 440 x 2 x 6
    transpose_kernel<<<tg, dim3(32, 8)>>>(feat);

    cudaFuncSetAttribute(fuse_kernel, cudaFuncAttributeMaxDynamicSharedMemorySize, SMEM_BYTES);
    fuse_kernel<<<NBLK, 256, SMEM_BYTES>>>(mask, K, ext, w_no, b_no, w_o, b_o, out);
}

// round 2
// speedup vs baseline: 1.1055x; 1.1055x over previous
#include <cuda_runtime.h>

#define NC    6
#define CF    64
#define Hh    88
#define Ww    160
#define HWp   (Hh*Ww)          // 14080
#define XD    100
#define YD    100
#define ZD    20
#define NVOX  (XD*YD*ZD)       // 200000
#define WARPS 8
#define NBLK  608              // 152 SMs * 4 blocks

// scratch: channel-last features [cam][H][W][C]
__device__ float g_featT[NC * HWp * CF];

// dynamic smem (floats/bytes):
//  float4 wno4[33*32]   16896
//  float4 wo4 [66*32]   33792
//  float  bno[64]+bo[64]  512
//  float  E[96]+K[96]     768
//  float  sout[64*17]    4352
#define SMEM_BYTES (16896 + 33792 + 512 + 768 + 4352)

__global__ void transpose_kernel(const float* __restrict__ feat) {
    __shared__ float tile[32][33];
    int cam = blockIdx.z;
    int c0  = blockIdx.y * 32;
    int p0  = blockIdx.x * 32;
    int tx = threadIdx.x, ty = threadIdx.y;
    const float* src = feat + (size_t)cam * CF * HWp;
#pragma unroll
    for (int i = ty; i < 32; i += 8)
        tile[i][tx] = src[(c0 + i) * HWp + p0 + tx];
    __syncthreads();
    float* dst = g_featT + (size_t)cam * HWp * CF;
#pragma unroll
    for (int i = ty; i < 32; i += 8)
        dst[(p0 + i) * CF + c0 + tx] = tile[tx][i];
}

__device__ __forceinline__ float elu1(float x) { return x > 0.f ? x : expm1f(x); }

// sample one voxel: returns count, accumulates group feats in registers
__device__ __forceinline__ int sample_voxel(
    int n, const float* __restrict__ s_E, const float* __restrict__ s_K,
    const float* __restrict__ mask, int lane,
    float& g0x, float& g0y, float& z0, float& g1x, float& g1y, float& z1)
{
    int x = n % XD;
    int y = (n / XD) % YD;
    int z = n / (XD * YD);
    float X = -50.f + (float)x;
    float Y = -50.f + (float)y;
    float Z = -15.f + 1.5f * (float)z;
    int count = 0;
#pragma unroll
    for (int cam = 0; cam < NC; cam++) {
        const float* E  = s_E + cam * 16;
        const float* Km = s_K + cam * 16;
        float vx = E[0] * X + E[1] * Y + E[2]  * Z + E[3];
        float vy = E[4] * X + E[5] * Y + E[6]  * Z + E[7];
        float vz = E[8] * X + E[9] * Y + E[10] * Z + E[11];
        if (!(vz > 0.f)) continue;                  // depth test first (cheap)
        float cx = Km[0] * vx + Km[1] * vy + Km[2]  * vz;
        float cy = Km[4] * vx + Km[5] * vy + Km[6]  * vz;
        float cz = Km[8] * vx + Km[9] * vy + Km[10] * vz;
        float denom = cz + 1e-8f;
        float px = __fdiv_rn(cx, denom);
        float py = __fdiv_rn(cy, denom);
        float gx = (__fdiv_rn(px, 159.f) - 0.5f) * 2.f;
        float gy = (__fdiv_rn(py,  87.f) - 0.5f) * 2.f;
        if (gx > 1.f || gx < -1.f || gy > 1.f || gy < -1.f) continue;  // oob
        float xs = (gx + 1.f) * 0.5f * 159.f;
        float ys = (gy + 1.f) * 0.5f * 87.f;
        float xr = rintf(xs), yr = rintf(ys);
        if (!(xr >= 0.f && xr <= 159.f && yr >= 0.f && yr <= 87.f)) continue;
        float mv = __ldg(mask + cam * HWp + (int)yr * Ww + (int)xr);
        if (!(mv > 0.5f)) continue;
        count++;
        // bilinear (align_corners, zeros padding)
        float x0 = floorf(xs), y0 = floorf(ys);
        float wx1 = xs - x0, wx0 = 1.f - wx1;
        float wy1 = ys - y0, wy0 = 1.f - wy1;
        float ax = 0.f, ay = 0.f;
        const float2* base = (const float2*)(g_featT + (size_t)cam * HWp * CF);
#pragma unroll
        for (int corner = 0; corner < 4; corner++) {
            float xi = x0 + (float)(corner & 1);
            float yi = y0 + (float)(corner >> 1);
            if (xi >= 0.f && xi <= 159.f && yi >= 0.f && yi <= 87.f) {
                float w = ((corner & 1) ? wx1 : wx0) * ((corner >> 1) ? wy1 : wy0);
                int pixi = (int)yi * Ww + (int)xi;
                float2 v = __ldg(base + pixi * 32 + lane);
                ax += w * v.x;
                ay += w * v.y;
            }
        }
        float dz = __fdiv_rn(vz, 100.f);
        if (cam == 0 || cam == 3 || cam == 4) { g0x += ax; g0y += ay; z0 += dz; }
        else                                  { g1x += ax; g1y += ay; z1 += dz; }
    }
    return count;
}

__device__ __forceinline__ void gemv_no1(
    const float4* __restrict__ w, int lane,
    float sx, float sy, float zz, float& o0, float& o1)
{
#pragma unroll
    for (int p = 0; p < 32; p++) {
        float4 w4 = w[p * 32 + lane];
        float f0 = __shfl_sync(0xFFFFFFFFu, sx, p);
        float f1 = __shfl_sync(0xFFFFFFFFu, sy, p);
        o0 = fmaf(w4.x, f0, o0); o1 = fmaf(w4.y, f0, o1);
        o0 = fmaf(w4.z, f1, o0); o1 = fmaf(w4.w, f1, o1);
    }
    float4 wz = w[32 * 32 + lane];
    o0 = fmaf(wz.x, zz, o0); o1 = fmaf(wz.y, zz, o1);
}

__device__ __forceinline__ void gemv_no2(
    const float4* __restrict__ w, int lane,
    float sxA, float syA, float zzA, float sxB, float syB, float zzB,
    float& o0A, float& o1A, float& o0B, float& o1B)
{
#pragma unroll
    for (int p = 0; p < 32; p++) {
        float4 w4 = w[p * 32 + lane];
        float fA0 = __shfl_sync(0xFFFFFFFFu, sxA, p);
        float fA1 = __shfl_sync(0xFFFFFFFFu, syA, p);
        float fB0 = __shfl_sync(0xFFFFFFFFu, sxB, p);
        float fB1 = __shfl_sync(0xFFFFFFFFu, syB, p);
        o0A = fmaf(w4.x, fA0, o0A); o1A = fmaf(w4.y, fA0, o1A);
        o0A = fmaf(w4.z, fA1, o0A); o1A = fmaf(w4.w, fA1, o1A);
        o0B = fmaf(w4.x, fB0, o0B); o1B = fmaf(w4.y, fB0, o1B);
        o0B = fmaf(w4.z, fB1, o0B); o1B = fmaf(w4.w, fB1, o1B);
    }
    float4 wz = w[32 * 32 + lane];
    o0A = fmaf(wz.x, zzA, o0A); o1A = fmaf(wz.y, zzA, o1A);
    o0B = fmaf(wz.x, zzB, o0B); o1B = fmaf(wz.y, zzB, o1B);
}

__device__ __forceinline__ void gemv_o1(
    const float4* __restrict__ w, int lane,
    float g0x, float g0y, float z0, float g1x, float g1y, float z1,
    float& o0, float& o1)
{
#pragma unroll
    for (int p = 0; p < 32; p++) {
        float4 w4 = w[p * 32 + lane];
        float f0 = __shfl_sync(0xFFFFFFFFu, g0x, p);
        float f1 = __shfl_sync(0xFFFFFFFFu, g0y, p);
        o0 = fmaf(w4.x, f0, o0); o1 = fmaf(w4.y, f0, o1);
        o0 = fmaf(w4.z, f1, o0); o1 = fmaf(w4.w, f1, o1);
    }
    { float4 wz = w[32 * 32 + lane];
      o0 = fmaf(wz.x, z0, o0); o1 = fmaf(wz.y, z0, o1); }
#pragma unroll
    for (int p = 0; p < 32; p++) {
        float4 w4 = w[(33 + p) * 32 + lane];
        float f0 = __shfl_sync(0xFFFFFFFFu, g1x, p);
        float f1 = __shfl_sync(0xFFFFFFFFu, g1y, p);
        o0 = fmaf(w4.x, f0, o0); o1 = fmaf(w4.y, f0, o1);
        o0 = fmaf(w4.z, f1, o0); o1 = fmaf(w4.w, f1, o1);
    }
    { float4 wz = w[65 * 32 + lane];
      o0 = fmaf(wz.x, z1, o0); o1 = fmaf(wz.y, z1, o1); }
}

__device__ __forceinline__ void gemv_o2(
    const float4* __restrict__ w, int lane,
    float g0xA, float g0yA, float z0A, float g1xA, float g1yA, float z1A,
    float g0xB, float g0yB, float z0B, float g1xB, float g1yB, float z1B,
    float& o0A, float& o1A, float& o0B, float& o1B)
{
#pragma unroll
    for (int p = 0; p < 32; p++) {
        float4 w4 = w[p * 32 + lane];
        float fA0 = __shfl_sync(0xFFFFFFFFu, g0xA, p);
        float fA1 = __shfl_sync(0xFFFFFFFFu, g0yA, p);
        float fB0 = __shfl_sync(0xFFFFFFFFu, g0xB, p);
        float fB1 = __shfl_sync(0xFFFFFFFFu, g0yB, p);
        o0A = fmaf(w4.x, fA0, o0A); o1A = fmaf(w4.y, fA0, o1A);
        o0A = fmaf(w4.z, fA1, o0A); o1A = fmaf(w4.w, fA1, o1A);
        o0B = fmaf(w4.x, fB0, o0B); o1B = fmaf(w4.y, fB0, o1B);
        o0B = fmaf(w4.z, fB1, o0B); o1B = fmaf(w4.w, fB1, o1B);
    }
    { float4 wz = w[32 * 32 + lane];
      o0A = fmaf(wz.x, z0A, o0A); o1A = fmaf(wz.y, z0A, o1A);
      o0B = fmaf(wz.x, z0B, o0B); o1B = fmaf(wz.y, z0B, o1B); }
#pragma unroll
    for (int p = 0; p < 32; p++) {
        float4 w4 = w[(33 + p) * 32 + lane];
        float fA0 = __shfl_sync(0xFFFFFFFFu, g1xA, p);
        float fA1 = __shfl_sync(0xFFFFFFFFu, g1yA, p);
        float fB0 = __shfl_sync(0xFFFFFFFFu, g1xB, p);
        float fB1 = __shfl_sync(0xFFFFFFFFu, g1yB, p);
        o0A = fmaf(w4.x, fA0, o0A); o1A = fmaf(w4.y, fA0, o1A);
        o0A = fmaf(w4.z, fA1, o0A); o1A = fmaf(w4.w, fA1, o1A);
        o0B = fmaf(w4.x, fB0, o0B); o1B = fmaf(w4.y, fB0, o1B);
        o0B = fmaf(w4.z, fB1, o0B); o1B = fmaf(w4.w, fB1, o1B);
    }
    { float4 wz = w[65 * 32 + lane];
      o0A = fmaf(wz.x, z1A, o0A); o1A = fmaf(wz.y, z1A, o1A);
      o0B = fmaf(wz.x, z1B, o0B); o1B = fmaf(wz.y, z1B, o1B); }
}

__global__ __launch_bounds__(256, 4) void fuse_kernel(
    const float* __restrict__ mask,   // [6,1,88,160]
    const float* __restrict__ Kin,    // [6,4,4]
    const float* __restrict__ Ein,    // [6,4,4]
    const float* __restrict__ w_no,   // [64,65]
    const float* __restrict__ b_no,   // [64]
    const float* __restrict__ w_o,    // [64,130]
    const float* __restrict__ b_o,    // [64]
    float* __restrict__ out)          // [64, NVOX]
{
    extern __shared__ float smem[];
    float4* s_wno4 = (float4*)smem;                  // 33*32
    float4* s_wo4  = s_wno4 + 33 * 32;               // 66*32
    float*  s_bno  = (float*)(s_wo4 + 66 * 32);      // 64
    float*  s_bo   = s_bno + 64;                     // 64
    float*  s_E    = s_bo + 64;                      // 96
    float*  s_K    = s_E + 96;                       // 96
    float*  s_out  = s_K + 96;                       // 64*17

    int tid = threadIdx.x;
    // pack w_no: pairs of channels (2p,2p+1) as float4 {w[l][2p], w[l+32][2p], w[l][2p+1], w[l+32][2p+1]}
    for (int i = tid; i < 33 * 32; i += 256) {
        int p = i >> 5, l = i & 31;
        float4 v;
        if (p < 32) {
            v.x = w_no[l * 65 + 2 * p];        v.y = w_no[(l + 32) * 65 + 2 * p];
            v.z = w_no[l * 65 + 2 * p + 1];    v.w = w_no[(l + 32) * 65 + 2 * p + 1];
        } else {  // z channel (col 64)
            v.x = w_no[l * 65 + 64];           v.y = w_no[(l + 32) * 65 + 64];
            v.z = 0.f;                         v.w = 0.f;
        }
        s_wno4[i] = v;
    }
    // pack w_o with a padded 132-channel layout: [g0(0..63), z0, PAD, g1(0..63), z1, PAD]
    for (int i = tid; i < 66 * 32; i += 256) {
        int p = i >> 5, l = i & 31;
        int q0 = 2 * p, q1 = 2 * p + 1;
        int c0 = (q0 < 65) ? q0 : ((q0 == 65 || q0 == 131) ? -1 : q0 - 1);
        int c1 = (q1 < 65) ? q1 : ((q1 == 65 || q1 == 131) ? -1 : q1 - 1);
        float4 v;
        v.x = (c0 >= 0) ? w_o[l * 130 + c0] : 0.f;
        v.y = (c0 >= 0) ? w_o[(l + 32) * 130 + c0] : 0.f;
        v.z = (c1 >= 0) ? w_o[l * 130 + c1] : 0.f;
        v.w = (c1 >= 0) ? w_o[(l + 32) * 130 + c1] : 0.f;
        s_wo4[i] = v;
    }
    if (tid < 64) { s_bno[tid] = b_no[tid]; s_bo[tid] = b_o[tid]; }
    if (tid < 96) { s_E[tid] = Ein[tid]; s_K[tid] = Kin[tid]; }
    __syncthreads();

    int warp = tid >> 5, lane = tid & 31;
    int nwarps = gridDim.x * WARPS;
    int stride = nwarps * 2;                   // voxels per grid-iter
    int T = (NVOX + stride - 1) / stride;

    for (int t = 0; t < T; t++) {
        int nbase = blockIdx.x * (WARPS * 2) + t * stride;   // block's 16 voxels
        int nA = nbase + 2 * warp;
        int nB = nA + 1;

        float g0xA = 0.f, g0yA = 0.f, z0A = 0.f, g1xA = 0.f, g1yA = 0.f, z1A = 0.f;
        float g0xB = 0.f, g0yB = 0.f, z0B = 0.f, g1xB = 0.f, g1yB = 0.f, z1B = 0.f;
        int cA = (nA < NVOX) ? sample_voxel(nA, s_E, s_K, mask, lane, g0xA, g0yA, z0A, g1xA, g1yA, z1A) : 0;
        int cB = (nB < NVOX) ? sample_voxel(nB, s_E, s_K, mask, lane, g0xB, g0yB, z0B, g1xB, g1yB, z1B) : 0;

        float o0A = 0.f, o1A = 0.f, o0B = 0.f, o1B = 0.f;
        if (cA == 1 && cB == 1) {
            gemv_no2(s_wno4, lane,
                     g0xA + g1xA, g0yA + g1yA, z0A + z1A,
                     g0xB + g1xB, g0yB + g1yB, z0B + z1B,
                     o0A, o1A, o0B, o1B);
        } else if (cA == 2 && cB == 2) {
            gemv_o2(s_wo4, lane,
                    g0xA, g0yA, z0A, g1xA, g1yA, z1A,
                    g0xB, g0yB, z0B, g1xB, g1yB, z1B,
                    o0A, o1A, o0B, o1B);
        } else {
            if (cA == 1)      gemv_no1(s_wno4, lane, g0xA + g1xA, g0yA + g1yA, z0A + z1A, o0A, o1A);
            else if (cA == 2) gemv_o1(s_wo4, lane, g0xA, g0yA, z0A, g1xA, g1yA, z1A, o0A, o1A);
            if (cB == 1)      gemv_no1(s_wno4, lane, g0xB + g1xB, g0yB + g1yB, z0B + z1B, o0B, o1B);
            else if (cB == 2) gemv_o1(s_wo4, lane, g0xB, g0yB, z0B, g1xB, g1yB, z1B, o0B, o1B);
        }
        if (cA == 1)      { o0A = elu1(o0A + s_bno[lane]); o1A = elu1(o1A + s_bno[lane + 32]); }
        else if (cA == 2) { o0A = elu1(o0A + s_bo[lane]);  o1A = elu1(o1A + s_bo[lane + 32]);  }
        if (cB == 1)      { o0B = elu1(o0B + s_bno[lane]); o1B = elu1(o1B + s_bno[lane + 32]); }
        else if (cB == 2) { o0B = elu1(o0B + s_bo[lane]);  o1B = elu1(o1B + s_bo[lane + 32]);  }

        // stage: s_out[o*17 + v], v = local voxel 0..15
        int vA = 2 * warp, vB = vA + 1;
        s_out[lane * 17 + vA]        = o0A;
        s_out[(lane + 32) * 17 + vA] = o1A;
        s_out[lane * 17 + vB]        = o0B;
        s_out[(lane + 32) * 17 + vB] = o1B;
        __syncthreads();
        // coalesced output: 64 rows x 16 consecutive voxels
#pragma unroll
        for (int i = tid; i < 1024; i += 256) {
            int o = i >> 4, v = i & 15;
            int nn = nbase + v;
            if (nn < NVOX) out[(size_t)o * NVOX + nn] = s_out[o * 17 + v];
        }
        __syncthreads();
    }
}

extern "C" void kernel_launch(void* const* d_in, const int* in_sizes, int n_in,
                              void* d_out, int out_size) {
    const float* feat = (const float*)d_in[0];
    const float* mask = (const float*)d_in[1];
    const float* K    = (const float*)d_in[2];
    const float* ext  = (const float*)d_in[3];
    const float* w_no = (const float*)d_in[4];
    const float* b_no = (const float*)d_in[5];
    const float* w_o  = (const float*)d_in[6];
    const float* b_o  = (const float*)d_in[7];
    float* out = (float*)d_out;

    dim3 tg(HWp / 32, CF / 32, NC);   // 440 x 2 x 6
    transpose_kernel<<<tg, dim3(32, 8)>>>(feat);

    cudaFuncSetAttribute(fuse_kernel, cudaFuncAttributeMaxDynamicSharedMemorySize, SMEM_BYTES);
    fuse_kernel<<<NBLK, 256, SMEM_BYTES>>>(mask, K, ext, w_no, b_no, w_o, b_o, out);
}

// round 3
// speedup vs baseline: 2.2650x; 2.0488x over previous
#include <cuda_runtime.h>

#define NC    6
#define CF    64
#define Hh    88
#define Ww    160
#define HWp   (Hh*Ww)          // 14080
#define XD    100
#define YD    100
#define ZD    20
#define NVOX  (XD*YD*ZD)       // 200000

// scratch
__device__ float  g_featT[NC * HWp * CF];   // channel-last features [cam][H][W][C]
__device__ float4 g_q1[NVOX * 2];           // count==1 records
__device__ float4 g_q2[NVOX * 2];           // count==2 records
__device__ int    g_cnt[2];

__device__ __forceinline__ float elu1(float x) { return x > 0.f ? x : expm1f(x); }

__global__ void transpose_kernel(const float* __restrict__ feat) {
    __shared__ float tile[32][33];
    if (blockIdx.x == 0 && blockIdx.y == 0 && blockIdx.z == 0 &&
        threadIdx.x == 0 && threadIdx.y == 0) { g_cnt[0] = 0; g_cnt[1] = 0; }
    int cam = blockIdx.z;
    int c0  = blockIdx.y * 32;
    int p0  = blockIdx.x * 32;
    int tx = threadIdx.x, ty = threadIdx.y;
    const float* src = feat + (size_t)cam * CF * HWp;
#pragma unroll
    for (int i = ty; i < 32; i += 8)
        tile[i][tx] = src[(c0 + i) * HWp + p0 + tx];
    __syncthreads();
    float* dst = g_featT + (size_t)cam * HWp * CF;
#pragma unroll
    for (int i = ty; i < 32; i += 8)
        dst[(p0 + i) * CF + c0 + tx] = tile[tx][i];
}

__global__ __launch_bounds__(256) void classify_kernel(
    const float* __restrict__ mask,
    const float* __restrict__ Kin,
    const float* __restrict__ Ein)
{
    __shared__ float sE[96], sK[96];
    __shared__ int sh_cnt[2], sh_base[2];
    int tid = threadIdx.x;
    if (tid < 96) { sE[tid] = Ein[tid]; sK[tid] = Kin[tid]; }
    if (tid < 2) sh_cnt[tid] = 0;
    __syncthreads();

    int n = blockIdx.x * 256 + tid;
    int count = 0, camA = 0, camB = 0;
    float xsA = 0.f, ysA = 0.f, xsB = 0.f, ysB = 0.f, z0 = 0.f, z1 = 0.f;
    if (n < NVOX) {
        int x = n % XD, y = (n / XD) % YD, z = n / (XD * YD);
        float X = -50.f + (float)x;
        float Y = -50.f + (float)y;
        float Z = -15.f + 1.5f * (float)z;
#pragma unroll
        for (int cam = 0; cam < NC; cam++) {
            const float* E  = sE + cam * 16;
            const float* Km = sK + cam * 16;
            float vx = E[0] * X + E[1] * Y + E[2]  * Z + E[3];
            float vy = E[4] * X + E[5] * Y + E[6]  * Z + E[7];
            float vz = E[8] * X + E[9] * Y + E[10] * Z + E[11];
            if (!(vz > 0.f)) continue;
            float cx = Km[0] * vx + Km[1] * vy + Km[2]  * vz;
            float cy = Km[4] * vx + Km[5] * vy + Km[6]  * vz;
            float cz = Km[8] * vx + Km[9] * vy + Km[10] * vz;
            float denom = cz + 1e-8f;
            float px = __fdiv_rn(cx, denom);
            float py = __fdiv_rn(cy, denom);
            float gx = (__fdiv_rn(px, 159.f) - 0.5f) * 2.f;
            float gy = (__fdiv_rn(py,  87.f) - 0.5f) * 2.f;
            if (gx > 1.f || gx < -1.f || gy > 1.f || gy < -1.f) continue;
            float xs = (gx + 1.f) * 0.5f * 159.f;
            float ys = (gy + 1.f) * 0.5f * 87.f;
            float xr = rintf(xs), yr = rintf(ys);
            if (!(xr >= 0.f && xr <= 159.f && yr >= 0.f && yr <= 87.f)) continue;
            float mv = __ldg(mask + cam * HWp + (int)yr * Ww + (int)xr);
            if (!(mv > 0.5f)) continue;
            if (count == 0)      { camA = cam; xsA = xs; ysA = ys; }
            else if (count == 1) { camB = cam; xsB = xs; ysB = ys; }
            count++;
            float dz = __fdiv_rn(vz, 100.f);
            if (cam == 0 || cam == 3 || cam == 4) z0 += dz; else z1 += dz;
        }
    }
    int lane = tid & 31;
    unsigned lt = (1u << lane) - 1u;
    unsigned m1 = __ballot_sync(0xFFFFFFFFu, count == 1);
    unsigned m2 = __ballot_sync(0xFFFFFFFFu, count == 2);
    int w1 = 0, w2o = 0;
    if (m1) {
        int ldr = __ffs(m1) - 1;
        if (lane == ldr) w1 = atomicAdd(&sh_cnt[0], __popc(m1));
        w1 = __shfl_sync(0xFFFFFFFFu, w1, ldr);
    }
    if (m2) {
        int ldr = __ffs(m2) - 1;
        if (lane == ldr) w2o = atomicAdd(&sh_cnt[1], __popc(m2));
        w2o = __shfl_sync(0xFFFFFFFFu, w2o, ldr);
    }
    __syncthreads();
    if (tid < 2) sh_base[tid] = atomicAdd(&g_cnt[tid], sh_cnt[tid]);
    __syncthreads();
    if (count == 1) {
        int idx = sh_base[0] + w1 + __popc(m1 & lt);
        g_q1[idx * 2]     = make_float4(__int_as_float(n), __int_as_float(camA), xsA, ysA);
        g_q1[idx * 2 + 1] = make_float4(z0 + z1, 0.f, 0.f, 0.f);
    } else if (count == 2) {
        int idx = sh_base[1] + w2o + __popc(m2 & lt);
        g_q2[idx * 2]     = make_float4(__int_as_float(n), __int_as_float(camA | (camB << 8)), xsA, ysA);
        g_q2[idx * 2 + 1] = make_float4(xsB, ysB, z0, z1);
    }
}

__device__ __forceinline__ float2 bilin(int cam, float xs, float ys, int lane) {
    float x0 = floorf(xs), y0 = floorf(ys);
    float wx1 = xs - x0, wx0 = 1.f - wx1;
    float wy1 = ys - y0, wy0 = 1.f - wy1;
    float ax = 0.f, ay = 0.f;
    const float2* base = (const float2*)(g_featT + (size_t)cam * HWp * CF);
#pragma unroll
    for (int corner = 0; corner < 4; corner++) {
        float xi = x0 + (float)(corner & 1);
        float yi = y0 + (float)(corner >> 1);
        if (xi >= 0.f && xi <= 159.f && yi >= 0.f && yi <= 87.f) {
            float w = ((corner & 1) ? wx1 : wx0) * ((corner >> 1) ? wy1 : wy0);
            int pixi = (int)yi * Ww + (int)xi;
            float2 v = __ldg(base + pixi * 32 + lane);
            ax += w * v.x;
            ay += w * v.y;
        }
    }
    return make_float2(ax, ay);
}

// Tiled GEMM over a queue: 64 outputs x 32 voxels per block tile, K = KR.
template<int KR, int QIDX>
__global__ __launch_bounds__(256) void gemm_kernel(
    const float* __restrict__ W,      // [64, KR] row-major
    const float* __restrict__ bias,   // [64]
    float* __restrict__ out)          // [64, NVOX]
{
    extern __shared__ float smem[];
    float2* w2  = (float2*)smem;                 // [KR][32] : {W[l][k], W[l+32][k]}
    float*  fsm = smem + KR * 32 * 2;            // [KR][36]
    float*  sb  = fsm + KR * 36;                 // [64]
    int*    s_n = (int*)(sb + 64);               // [32]

    int tid = threadIdx.x, lane = tid & 31, warp = tid >> 5;
    for (int i = tid; i < KR * 32; i += 256) {
        int k = i >> 5, l = i & 31;
        w2[i] = make_float2(W[l * KR + k], W[(l + 32) * KR + k]);
    }
    if (tid < 64) sb[tid] = bias[tid];
    int total = g_cnt[QIDX];
    __syncthreads();

    const float4* q = QIDX ? g_q2 : g_q1;
    for (int tile = blockIdx.x; tile * 32 < total; tile += gridDim.x) {
        // ---- gather: each warp fills 4 columns ----
#pragma unroll
        for (int j = 0; j < 4; j++) {
            int v = warp + j * 8;
            int r = tile * 32 + v;
            if (r < total) {
                float4 ra = __ldg(q + r * 2);
                float4 rb = __ldg(q + r * 2 + 1);
                int n = __float_as_int(ra.x);
                if (QIDX == 0) {
                    int cam = __float_as_int(ra.y);
                    float2 a = bilin(cam, ra.z, ra.w, lane);
                    fsm[(2 * lane) * 36 + v]     = a.x;
                    fsm[(2 * lane + 1) * 36 + v] = a.y;
                    if (lane == 0) { fsm[64 * 36 + v] = rb.x; s_n[v] = n; }
                } else {
                    int cc = __float_as_int(ra.y);
                    int camA = cc & 255, camB = cc >> 8;
                    float2 a = bilin(camA, ra.z, ra.w, lane);
                    float2 b = bilin(camB, rb.x, rb.y, lane);
                    float2 h0 = make_float2(0.f, 0.f), h1 = make_float2(0.f, 0.f);
                    if (camA == 0 || camA == 3 || camA == 4) { h0.x += a.x; h0.y += a.y; }
                    else                                     { h1.x += a.x; h1.y += a.y; }
                    if (camB == 0 || camB == 3 || camB == 4) { h0.x += b.x; h0.y += b.y; }
                    else                                     { h1.x += b.x; h1.y += b.y; }
                    fsm[(2 * lane) * 36 + v]          = h0.x;
                    fsm[(2 * lane + 1) * 36 + v]      = h0.y;
                    fsm[(65 + 2 * lane) * 36 + v]     = h1.x;
                    fsm[(65 + 2 * lane + 1) * 36 + v] = h1.y;
                    if (lane == 0) { fsm[64 * 36 + v] = rb.z; fsm[129 * 36 + v] = rb.w; s_n[v] = n; }
                }
            } else if (lane == 0) s_n[v] = -1;
        }
        __syncthreads();
        // ---- GEMM: thread = (o=lane, o=lane+32) x 4 voxels (warp's v-group) ----
        float a00=0.f,a01=0.f,a10=0.f,a11=0.f,a20=0.f,a21=0.f,a30=0.f,a31=0.f;
        const float* fb = fsm + warp * 4;
#pragma unroll 5
        for (int k = 0; k < KR; k++) {
            float2 wv = w2[k * 32 + lane];
            float4 fv = *(const float4*)(fb + k * 36);
            a00 = fmaf(wv.x, fv.x, a00); a01 = fmaf(wv.y, fv.x, a01);
            a10 = fmaf(wv.x, fv.y, a10); a11 = fmaf(wv.y, fv.y, a11);
            a20 = fmaf(wv.x, fv.z, a20); a21 = fmaf(wv.y, fv.z, a21);
            a30 = fmaf(wv.x, fv.w, a30); a31 = fmaf(wv.y, fv.w, a31);
        }
        float b0 = sb[lane], b1 = sb[lane + 32];
        int vb = warp * 4;
        int nn;
        nn = s_n[vb];     if (nn >= 0) { out[(size_t)lane * NVOX + nn] = elu1(a00 + b0); out[(size_t)(lane + 32) * NVOX + nn] = elu1(a01 + b1); }
        nn = s_n[vb + 1]; if (nn >= 0) { out[(size_t)lane * NVOX + nn] = elu1(a10 + b0); out[(size_t)(lane + 32) * NVOX + nn] = elu1(a11 + b1); }
        nn = s_n[vb + 2]; if (nn >= 0) { out[(size_t)lane * NVOX + nn] = elu1(a20 + b0); out[(size_t)(lane + 32) * NVOX + nn] = elu1(a21 + b1); }
        nn = s_n[vb + 3]; if (nn >= 0) { out[(size_t)lane * NVOX + nn] = elu1(a30 + b0); out[(size_t)(lane + 32) * NVOX + nn] = elu1(a31 + b1); }
        __syncthreads();
    }
}

extern "C" void kernel_launch(void* const* d_in, const int* in_sizes, int n_in,
                              void* d_out, int out_size) {
    const float* feat = (const float*)d_in[0];
    const float* mask = (const float*)d_in[1];
    const float* K    = (const float*)d_in[2];
    const float* ext  = (const float*)d_in[3];
    const float* w_no = (const float*)d_in[4];
    const float* b_no = (const float*)d_in[5];
    const float* w_o  = (const float*)d_in[6];
    const float* b_o  = (const float*)d_in[7];
    float* out = (float*)d_out;

    dim3 tg(HWp / 32, CF / 32, NC);   // 440 x 2 x 6
    transpose_kernel<<<tg, dim3(32, 8)>>>(feat);

    cudaMemsetAsync(d_out, 0, (size_t)out_size * sizeof(float), 0);

    classify_kernel<<<(NVOX + 255) / 256, 256>>>(mask, K, ext);

    const int smem1 = 65 * 32 * 2 * 4 + 65 * 36 * 4 + 64 * 4 + 32 * 4;    // 26384
    const int smem2 = 130 * 32 * 2 * 4 + 130 * 36 * 4 + 64 * 4 + 32 * 4;  // 52384
    cudaFuncSetAttribute(gemm_kernel<65, 0>,  cudaFuncAttributeMaxDynamicSharedMemorySize, smem1);
    cudaFuncSetAttribute(gemm_kernel<130, 1>, cudaFuncAttributeMaxDynamicSharedMemorySize, smem2);
    gemm_kernel<65, 0><<<608, 256, smem1>>>(w_no, b_no, out);
    gemm_kernel<130, 1><<<608, 256, smem2>>>(w_o, b_o, out);
}

// round 4
// speedup vs baseline: 3.4315x; 1.5150x over previous
#include <cuda_runtime.h>

#define NC    6
#define CF    64
#define Hh    88
#define Ww    160
#define HWp   (Hh*Ww)          // 14080
#define XD    100
#define YD    100
#define ZD    20
#define NVOX  (XD*YD*ZD)       // 200000

// scratch
__device__ float  g_featT[NC * HWp * CF];   // channel-last features [cam][H][W][C]
__device__ float4 g_q1[NVOX * 2];           // count==1 records
__device__ float4 g_q2[NVOX * 2];           // count==2 records
__device__ int    g_cnt[2];

__device__ __forceinline__ float elu1(float x) { return x > 0.f ? x : expm1f(x); }

__global__ void init_kernel() {
    if (threadIdx.x < 2) g_cnt[threadIdx.x] = 0;
}

__global__ void transpose_kernel(const float* __restrict__ feat) {
    __shared__ float tile[32][33];
    int cam = blockIdx.z;
    int c0  = blockIdx.y * 32;
    int p0  = blockIdx.x * 32;
    int tx = threadIdx.x, ty = threadIdx.y;
    const float* src = feat + (size_t)cam * CF * HWp;
#pragma unroll
    for (int i = ty; i < 32; i += 8)
        tile[i][tx] = src[(c0 + i) * HWp + p0 + tx];
    __syncthreads();
    float* dst = g_featT + (size_t)cam * HWp * CF;
#pragma unroll
    for (int i = ty; i < 32; i += 8)
        dst[(p0 + i) * CF + c0 + tx] = tile[tx][i];
}

__global__ __launch_bounds__(256) void classify_kernel(
    const float* __restrict__ mask,
    const float* __restrict__ Kin,
    const float* __restrict__ Ein,
    float* __restrict__ out)
{
    __shared__ float sE[96], sK[96];
    __shared__ int sh_cnt[2], sh_base[2];
    int tid = threadIdx.x;
    if (tid < 96) { sE[tid] = Ein[tid]; sK[tid] = Kin[tid]; }
    if (tid < 2) sh_cnt[tid] = 0;
    __syncthreads();

    int n = blockIdx.x * 256 + tid;
    int count = 0, camA = 0, camB = 0;
    float xsA = 0.f, ysA = 0.f, xsB = 0.f, ysB = 0.f, z0 = 0.f, z1 = 0.f;
    if (n < NVOX) {
        int x = n % XD, y = (n / XD) % YD, z = n / (XD * YD);
        float X = -50.f + (float)x;
        float Y = -50.f + (float)y;
        float Z = -15.f + 1.5f * (float)z;
#pragma unroll
        for (int cam = 0; cam < NC; cam++) {
            const float* E  = sE + cam * 16;
            const float* Km = sK + cam * 16;
            float vx = E[0] * X + E[1] * Y + E[2]  * Z + E[3];
            float vy = E[4] * X + E[5] * Y + E[6]  * Z + E[7];
            float vz = E[8] * X + E[9] * Y + E[10] * Z + E[11];
            if (!(vz > 0.f)) continue;
            float cx = Km[0] * vx + Km[1] * vy + Km[2]  * vz;
            float cy = Km[4] * vx + Km[5] * vy + Km[6]  * vz;
            float cz = Km[8] * vx + Km[9] * vy + Km[10] * vz;
            float denom = cz + 1e-8f;
            float px = __fdiv_rn(cx, denom);
            float py = __fdiv_rn(cy, denom);
            float gx = (__fdiv_rn(px, 159.f) - 0.5f) * 2.f;
            float gy = (__fdiv_rn(py,  87.f) - 0.5f) * 2.f;
            if (gx > 1.f || gx < -1.f || gy > 1.f || gy < -1.f) continue;
            float xs = (gx + 1.f) * 0.5f * 159.f;
            float ys = (gy + 1.f) * 0.5f * 87.f;
            float xr = rintf(xs), yr = rintf(ys);
            if (!(xr >= 0.f && xr <= 159.f && yr >= 0.f && yr <= 87.f)) continue;
            float mv = __ldg(mask + cam * HWp + (int)yr * Ww + (int)xr);
            if (!(mv > 0.5f)) continue;
            if (count == 0)      { camA = cam; xsA = xs; ysA = ys; }
            else if (count == 1) { camB = cam; xsB = xs; ysB = ys; }
            count++;
            float dz = __fdiv_rn(vz, 100.f);
            if (cam == 0 || cam == 3 || cam == 4) z0 += dz; else z1 += dz;
        }
    }
    int lane = tid & 31;
    unsigned lt = (1u << lane) - 1u;
    unsigned m1 = __ballot_sync(0xFFFFFFFFu, count == 1);
    unsigned m2 = __ballot_sync(0xFFFFFFFFu, count == 2);
    int w1 = 0, w2o = 0;
    if (m1) {
        int ldr = __ffs(m1) - 1;
        if (lane == ldr) w1 = atomicAdd(&sh_cnt[0], __popc(m1));
        w1 = __shfl_sync(0xFFFFFFFFu, w1, ldr);
    }
    if (m2) {
        int ldr = __ffs(m2) - 1;
        if (lane == ldr) w2o = atomicAdd(&sh_cnt[1], __popc(m2));
        w2o = __shfl_sync(0xFFFFFFFFu, w2o, ldr);
    }
    __syncthreads();
    if (tid < 2) sh_base[tid] = atomicAdd(&g_cnt[tid], sh_cnt[tid]);
    __syncthreads();
    if (n < NVOX) {
        if (count == 1) {
            int idx = sh_base[0] + w1 + __popc(m1 & lt);
            g_q1[idx * 2]     = make_float4(__int_as_float(n), __int_as_float(camA), xsA, ysA);
            g_q1[idx * 2 + 1] = make_float4(z0 + z1, 0.f, 0.f, 0.f);
        } else if (count == 2) {
            int idx = sh_base[1] + w2o + __popc(m2 & lt);
            g_q2[idx * 2]     = make_float4(__int_as_float(n), __int_as_float(camA | (camB << 8)), xsA, ysA);
            g_q2[idx * 2 + 1] = make_float4(xsB, ysB, z0, z1);
        } else {
            // inactive voxel: zero-fill its output column (replaces global memset)
#pragma unroll
            for (int o = 0; o < 64; o++) out[(size_t)o * NVOX + n] = 0.f;
        }
    }
}

__device__ __forceinline__ float2 bilin(int cam, float xs, float ys, int lane) {
    float x0 = floorf(xs), y0 = floorf(ys);
    float wx1 = xs - x0, wx0 = 1.f - wx1;
    float wy1 = ys - y0, wy0 = 1.f - wy1;
    float ax = 0.f, ay = 0.f;
    const float2* base = (const float2*)(g_featT + (size_t)cam * HWp * CF);
#pragma unroll
    for (int corner = 0; corner < 4; corner++) {
        float xi = x0 + (float)(corner & 1);
        float yi = y0 + (float)(corner >> 1);
        if (xi >= 0.f && xi <= 159.f && yi >= 0.f && yi <= 87.f) {
            float w = ((corner & 1) ? wx1 : wx0) * ((corner >> 1) ? wy1 : wy0);
            int pixi = (int)yi * Ww + (int)xi;
            float2 v = __ldg(base + pixi * 32 + lane);
            ax += w * v.x;
            ay += w * v.y;
        }
    }
    return make_float2(ax, ay);
}

// Tiled GEMM over a queue: 64 outputs x 64 voxels per block tile, K = KR.
template<int KR, int QIDX>
__global__ __launch_bounds__(256) void gemm_kernel(
    const float* __restrict__ W,      // [64, KR] row-major
    const float* __restrict__ bias,   // [64]
    float* __restrict__ out)          // [64, NVOX]
{
    extern __shared__ float smem[];
    float2* w2  = (float2*)smem;                 // [KR][32] : {W[l][k], W[l+32][k]}
    float*  fsm = smem + KR * 64;                // [KR][68] feats (aliased as sout[64][65] later)
    float*  sb  = fsm + KR * 68;                 // [64]
    int*    s_n = (int*)(sb + 64);               // [64]

    int total = g_cnt[QIDX];
    if (blockIdx.x * 64 >= total) return;        // early exit BEFORE weight load

    int tid = threadIdx.x, lane = tid & 31, warp = tid >> 5;
    for (int i = tid; i < KR * 32; i += 256) {
        int k = i >> 5, l = i & 31;
        w2[i] = make_float2(W[l * KR + k], W[(l + 32) * KR + k]);
    }
    if (tid < 64) sb[tid] = bias[tid];

    const float4* q = QIDX ? g_q2 : g_q1;
    for (int tile = blockIdx.x; tile * 64 < total; tile += gridDim.x) {
        __syncthreads();   // weights ready / previous write-out done reading fsm alias
        // ---- gather: warp w fills columns [w*8, w*8+8) ----
#pragma unroll
        for (int j = 0; j < 8; j++) {
            int v = warp * 8 + j;
            int r = tile * 64 + v;
            if (r < total) {
                float4 ra = __ldg(q + r * 2);
                float4 rb = __ldg(q + r * 2 + 1);
                int n = __float_as_int(ra.x);
                if (QIDX == 0) {
                    int cam = __float_as_int(ra.y);
                    float2 a = bilin(cam, ra.z, ra.w, lane);
                    fsm[(2 * lane) * 68 + v]     = a.x;
                    fsm[(2 * lane + 1) * 68 + v] = a.y;
                    if (lane == 0) { fsm[64 * 68 + v] = rb.x; s_n[v] = n; }
                } else {
                    int cc = __float_as_int(ra.y);
                    int camA = cc & 255, camB = cc >> 8;
                    float2 a = bilin(camA, ra.z, ra.w, lane);
                    float2 b = bilin(camB, rb.x, rb.y, lane);
                    float2 h0 = make_float2(0.f, 0.f), h1 = make_float2(0.f, 0.f);
                    if (camA == 0 || camA == 3 || camA == 4) { h0.x += a.x; h0.y += a.y; }
                    else                                     { h1.x += a.x; h1.y += a.y; }
                    if (camB == 0 || camB == 3 || camB == 4) { h0.x += b.x; h0.y += b.y; }
                    else                                     { h1.x += b.x; h1.y += b.y; }
                    fsm[(2 * lane) * 68 + v]          = h0.x;
                    fsm[(2 * lane + 1) * 68 + v]      = h0.y;
                    fsm[(65 + 2 * lane) * 68 + v]     = h1.x;
                    fsm[(65 + 2 * lane + 1) * 68 + v] = h1.y;
                    if (lane == 0) { fsm[64 * 68 + v] = rb.z; fsm[129 * 68 + v] = rb.w; s_n[v] = n; }
                }
            } else if (lane == 0) s_n[v] = -1;
        }
        __syncthreads();
        // ---- GEMM: warp w -> voxels [w*8, w*8+8), thread -> outputs (lane, lane+32) ----
        float acc[16];
#pragma unroll
        for (int i = 0; i < 16; i++) acc[i] = 0.f;
        int vb = warp * 8;
#pragma unroll 5
        for (int k = 0; k < KR; k++) {
            float2 wv = w2[k * 32 + lane];
            float4 f0 = *(const float4*)(fsm + k * 68 + vb);
            float4 f1 = *(const float4*)(fsm + k * 68 + vb + 4);
            acc[0]  = fmaf(wv.x, f0.x, acc[0]);  acc[1]  = fmaf(wv.y, f0.x, acc[1]);
            acc[2]  = fmaf(wv.x, f0.y, acc[2]);  acc[3]  = fmaf(wv.y, f0.y, acc[3]);
            acc[4]  = fmaf(wv.x, f0.z, acc[4]);  acc[5]  = fmaf(wv.y, f0.z, acc[5]);
            acc[6]  = fmaf(wv.x, f0.w, acc[6]);  acc[7]  = fmaf(wv.y, f0.w, acc[7]);
            acc[8]  = fmaf(wv.x, f1.x, acc[8]);  acc[9]  = fmaf(wv.y, f1.x, acc[9]);
            acc[10] = fmaf(wv.x, f1.y, acc[10]); acc[11] = fmaf(wv.y, f1.y, acc[11]);
            acc[12] = fmaf(wv.x, f1.z, acc[12]); acc[13] = fmaf(wv.y, f1.z, acc[13]);
            acc[14] = fmaf(wv.x, f1.w, acc[14]); acc[15] = fmaf(wv.y, f1.w, acc[15]);
        }
        __syncthreads();   // everyone done reading fsm; reuse as sout[64][65]
        float* som = fsm;
        float b0 = sb[lane], b1 = sb[lane + 32];
#pragma unroll
        for (int j = 0; j < 8; j++) {
            som[lane * 65 + vb + j]        = elu1(acc[2 * j]     + b0);
            som[(lane + 32) * 65 + vb + j] = elu1(acc[2 * j + 1] + b1);
        }
        __syncthreads();
        // ---- write-out: row-major, near-coalesced over clustered queue columns ----
#pragma unroll
        for (int i = tid; i < 64 * 64; i += 256) {
            int o = i >> 6, v = i & 63;
            int nn = s_n[v];
            if (nn >= 0) out[(size_t)o * NVOX + nn] = som[o * 65 + v];
        }
    }
}

extern "C" void kernel_launch(void* const* d_in, const int* in_sizes, int n_in,
                              void* d_out, int out_size) {
    const float* feat = (const float*)d_in[0];
    const float* mask = (const float*)d_in[1];
    const float* K    = (const float*)d_in[2];
    const float* ext  = (const float*)d_in[3];
    const float* w_no = (const float*)d_in[4];
    const float* b_no = (const float*)d_in[5];
    const float* w_o  = (const float*)d_in[6];
    const float* b_o  = (const float*)d_in[7];
    float* out = (float*)d_out;

    static cudaStream_t s1 = nullptr;
    static cudaEvent_t e0 = nullptr, e_t = nullptr, e_c = nullptr, e_g1 = nullptr;
    if (!s1) {
        cudaStreamCreateWithFlags(&s1, cudaStreamNonBlocking);
        cudaEventCreateWithFlags(&e0,  cudaEventDisableTiming);
        cudaEventCreateWithFlags(&e_t, cudaEventDisableTiming);
        cudaEventCreateWithFlags(&e_c, cudaEventDisableTiming);
        cudaEventCreateWithFlags(&e_g1, cudaEventDisableTiming);
    }

    const int smem1 = (65 * 64  + 65 * 68  + 64 + 64) * 4;   // 34832
    const int smem2 = (130 * 64 + 130 * 68 + 64 + 64) * 4;   // 69152
    cudaFuncSetAttribute(gemm_kernel<65, 0>,  cudaFuncAttributeMaxDynamicSharedMemorySize, smem1);
    cudaFuncSetAttribute(gemm_kernel<130, 1>, cudaFuncAttributeMaxDynamicSharedMemorySize, smem2);

    init_kernel<<<1, 32>>>();

    // fork: transpose on s1, classify (+zero-fill) on capture stream
    cudaEventRecord(e0, 0);
    cudaStreamWaitEvent(s1, e0, 0);

    dim3 tg(HWp / 32, CF / 32, NC);   // 440 x 2 x 6
    transpose_kernel<<<tg, dim3(32, 8), 0, s1>>>(feat);
    cudaEventRecord(e_t, s1);

    classify_kernel<<<(NVOX + 255) / 256, 256>>>(mask, K, ext, out);
    cudaEventRecord(e_c, 0);

    // join both, then fork the two GEMMs
    cudaStreamWaitEvent(0, e_t, 0);
    cudaStreamWaitEvent(s1, e_c, 0);

    gemm_kernel<130, 1><<<304, 256, smem2, 0>>>(w_o, b_o, out);
    gemm_kernel<65, 0><<<304, 256, smem1, s1>>>(w_no, b_no, out);
    cudaEventRecord(e_g1, s1);
    cudaStreamWaitEvent(0, e_g1, 0);
}